// round 17
// baseline (speedup 1.0000x reference)
#include <cuda_runtime.h>
#include <cuda_bf16.h>
#include <cuda_fp16.h>
#include <math.h>
#include <cstdint>

// Problem dims
#define TGT   64
#define SRC   64
#define BATCH 32
#define HID   512
#define ATT   512

// Scratch (no cudaMalloc allowed)
__device__ float g_hpart[TGT * BATCH * ATT];   // [t*BATCH+b][a]
__device__ float g_spart[SRC * BATCH * ATT];   // [s*BATCH+b][a]
__device__ __align__(16) __half g_attn[TGT * BATCH * SRC];   // fp16 attn [t][b][s]
__device__ __align__(16) __half g_Ah[2 * TGT * BATCH * HID]; // fp16 [h_t|src]
__device__ __align__(16) __half g_Bh[2 * HID * ATT];         // fp16 Wa^T: [z][n][k]
__device__ __align__(16) __half g_SrcT[BATCH * HID * SRC];   // fp16 src^T: [b][h][s]

// ---------------------------------------------------------------------------
// helpers
// ---------------------------------------------------------------------------
__device__ __forceinline__ float tanh_fast(float x) {
    float y;
    asm("tanh.approx.f32 %0, %1;" : "=f"(y) : "f"(x));
    return y;
}
__device__ __forceinline__ uint32_t smem_u32(const void* p) {
    uint32_t a;
    asm("{ .reg .u64 t; cvta.to.shared.u64 t, %1; cvt.u32.u64 %0, t; }"
        : "=r"(a) : "l"(p));
    return a;
}
#define CP_ASYNC16(dst, srcp) \
    asm volatile("cp.async.cg.shared.global [%0], [%1], 16;" :: "r"(dst), "l"(srcp))
#define CP_COMMIT() asm volatile("cp.async.commit_group;" ::: "memory")
#define CP_WAIT1()  asm volatile("cp.async.wait_group 1;" ::: "memory")
#define CP_WAIT0()  asm volatile("cp.async.wait_group 0;" ::: "memory")

#define LDSM_X4(r, addr)                                                       \
    asm volatile("ldmatrix.sync.aligned.m8n8.x4.shared.b16 {%0,%1,%2,%3}, [%4];" \
        : "=r"((r)[0]), "=r"((r)[1]), "=r"((r)[2]), "=r"((r)[3]) : "r"(addr))

// fp16 mma: D(f32) += A(f16) * B(f16), m16n8k16
__device__ __forceinline__ void mma_f16(float* c, const uint32_t* a, const uint32_t* b) {
    asm volatile(
        "mma.sync.aligned.m16n8k16.row.col.f32.f16.f16.f32 "
        "{%0,%1,%2,%3}, {%4,%5,%6,%7}, {%8,%9}, {%0,%1,%2,%3};"
        : "+f"(c[0]), "+f"(c[1]), "+f"(c[2]), "+f"(c[3])
        : "r"(a[0]), "r"(a[1]), "r"(a[2]), "r"(a[3]), "r"(b[0]), "r"(b[1]));
}

// ---------------------------------------------------------------------------
// Kernel 0: fp16 pre-pass, v2 — fewer blocks, 16B vectorized transposed stores.
//  bx 0..127:    g_Ah = half([h_t | src])           (grid-stride)
//  bx 128..255:  g_Bh[z][n][k]  = half(Wa[z*512+k][n])   (4 tiles/block)
//  bx 256..511:  g_SrcT[b][h][s] = half(src[s][b][h])    (4 tiles/block)
// ---------------------------------------------------------------------------
#define A4TOT (2 * TGT * BATCH * HID / 4)   // 524288 float4

__global__ __launch_bounds__(256) void prep_fp16(
    const float* __restrict__ h_t,
    const float* __restrict__ src,
    const float* __restrict__ Wa)
{
    const int bx  = blockIdx.x;
    const int tid = threadIdx.x;

    if (bx < 128) {
        for (int i = bx * 256 + tid; i < A4TOT; i += 128 * 256) {
            float4 v = (i < A4TOT / 2) ? ((const float4*)h_t)[i]
                                       : ((const float4*)src)[i - A4TOT / 2];
            __half2 lo = __float22half2_rn(make_float2(v.x, v.y));
            __half2 hi = __float22half2_rn(make_float2(v.z, v.w));
            uint2 pk;
            pk.x = *(uint32_t*)&lo;
            pk.y = *(uint32_t*)&hi;
            ((uint2*)g_Ah)[i] = pk;
        }
    } else if (bx < 256) {
        __shared__ float t[32][33];
        const int tx = tid & 31, ty = tid >> 5;
        const int wn = tid >> 2, wc = tid & 3;   // write mapping (128 active)
#pragma unroll
        for (int ti = 0; ti < 4; ti++) {
            const int tile = (bx - 128) * 4 + ti;   // 0..511
            const int z  = tile >> 8;
            const int rm = tile & 255;
            const int k0 = (rm & 15) * 32;
            const int n0 = (rm >> 4) * 32;
#pragma unroll
            for (int r = 0; r < 32; r += 8)
                t[ty + r][tx] = Wa[(z * HID + k0 + ty + r) * ATT + n0 + tx];
            __syncthreads();
            if (tid < 128) {
                __half h8[8];
#pragma unroll
                for (int j = 0; j < 8; j++)
                    h8[j] = __float2half_rn(t[wc * 8 + j][wn]);
                *(uint4*)&g_Bh[z * HID * ATT + (n0 + wn) * HID + k0 + wc * 8] =
                    *(uint4*)h8;
            }
            __syncthreads();
        }
    } else {
        __shared__ float t[32][33];
        const int tx = tid & 31, ty = tid >> 5;
        const int wn = tid >> 2, wc = tid & 3;
#pragma unroll
        for (int ti = 0; ti < 4; ti++) {
            const int tile = (bx - 256) * 4 + ti;   // 0..1023
            const int b  = tile >> 5;               // 0..31
            const int rm = tile & 31;
            const int s0 = (rm & 1) * 32;           // 0,32
            const int h0 = (rm >> 1) * 32;          // 0..480
#pragma unroll
            for (int r = 0; r < 32; r += 8)
                t[ty + r][tx] = src[((s0 + ty + r) * BATCH + b) * HID + h0 + tx];
            __syncthreads();
            if (tid < 128) {
                __half h8[8];
#pragma unroll
                for (int j = 0; j < 8; j++)
                    h8[j] = __float2half_rn(t[wc * 8 + j][wn]);
                *(uint4*)&g_SrcT[(b * HID + h0 + wn) * SRC + s0 + wc * 8] =
                    *(uint4*)h8;
            }
            __syncthreads();
        }
    }
}

// ---------------------------------------------------------------------------
// Kernel 1: fp16 mma GEMM. (R14, unchanged — passing)
// ---------------------------------------------------------------------------
#define KTH    64
#define RSH    72
#define ASTGH  (128 * RSH)
#define BSTGH  (64 * RSH)
#define STGH   (ASTGH + BSTGH)

__global__ __launch_bounds__(256, 2) void gemm_mma_h(void)
{
    extern __shared__ __align__(16) __half smh[];
    const uint32_t smb = smem_u32(smh);

    const int tid  = threadIdx.x;
    const int lane = tid & 31;
    const int wid  = tid >> 5;
    const int g    = lane >> 2;
    const int tg   = lane & 3;

    const int wm = (wid >> 1) * 32;
    const int wn = (wid & 1) * 32;

    const int ntile = blockIdx.x;
    const int mtile = blockIdx.y;
    const int z  = mtile >> 4;
    const int m0 = (mtile & 15) * 128;
    const int n0 = ntile * 64;
    const __half* A = g_Ah + z * (TGT * BATCH * HID);
    const __half* B = g_Bh + z * (HID * ATT);
    float*        C = (z == 0) ? g_hpart : g_spart;

    const uint32_t aoff = (uint32_t)(((wm + (lane & 15)) * RSH + ((lane >> 4) << 3)) * 2);
    const uint32_t boff0 = (uint32_t)((ASTGH +
        (wn + (((lane >> 4) & 1) << 3) + (lane & 7)) * RSH + (((lane >> 3) & 1) << 3)) * 2);
    const uint32_t boff1 = boff0 + (uint32_t)(16 * RSH * 2);

    auto stage = [&](int s, int bufi) {
        const int kt = s * KTH;
        const uint32_t bufA = smb + (uint32_t)(bufi * STGH) * 2u;
        const uint32_t bufB = bufA + (uint32_t)ASTGH * 2u;
#pragma unroll
        for (int r = 0; r < 4; r++) {
            const int idx = r * 256 + tid;
            const int am = idx >> 3, ac = idx & 7;
            CP_ASYNC16(bufA + (uint32_t)(am * RSH + ac * 8) * 2u,
                       A + (m0 + am) * HID + kt + ac * 8);
        }
#pragma unroll
        for (int r = 0; r < 2; r++) {
            const int idx = r * 256 + tid;
            const int bn = idx >> 3, bc = idx & 7;
            CP_ASYNC16(bufB + (uint32_t)(bn * RSH + bc * 8) * 2u,
                       B + (n0 + bn) * HID + kt + bc * 8);
        }
    };

    float acc[2][4][4];
#pragma unroll
    for (int mi = 0; mi < 2; mi++)
#pragma unroll
        for (int ni = 0; ni < 4; ni++)
#pragma unroll
            for (int j = 0; j < 4; j++) acc[mi][ni][j] = 0.f;

    stage(0, 0); CP_COMMIT();
    stage(1, 1); CP_COMMIT();

    for (int s = 0; s < 8; s++) {
        if (s < 7) CP_WAIT1(); else CP_WAIT0();
        __syncthreads();
        if (s + 2 < 8) { stage(s + 2, (s + 2) % 3); CP_COMMIT(); }

        const uint32_t base = smb + (uint32_t)((s % 3) * STGH) * 2u;
#pragma unroll
        for (int ks = 0; ks < 4; ks++) {
            const uint32_t koff = (uint32_t)(ks * 32);
            uint32_t a[2][4], b2[2][4];
            LDSM_X4(a[0], base + aoff + koff);
            LDSM_X4(a[1], base + aoff + (uint32_t)(16 * RSH * 2) + koff);
            LDSM_X4(b2[0], base + boff0 + koff);
            LDSM_X4(b2[1], base + boff1 + koff);
#pragma unroll
            for (int mi = 0; mi < 2; mi++)
#pragma unroll
                for (int ni = 0; ni < 4; ni++)
                    mma_f16(acc[mi][ni], a[mi], &b2[ni >> 1][(ni & 1) * 2]);
        }
    }

#pragma unroll
    for (int mi = 0; mi < 2; mi++) {
#pragma unroll
        for (int ni = 0; ni < 4; ni++) {
            const int row = m0 + wm + mi * 16 + g;
            const int col = n0 + wn + ni * 8 + 2 * tg;
            *(float2*)(C + row * ATT + col)       = make_float2(acc[mi][ni][0], acc[mi][ni][1]);
            *(float2*)(C + (row + 8) * ATT + col) = make_float2(acc[mi][ni][2], acc[mi][ni][3]);
        }
    }
}

// ---------------------------------------------------------------------------
// Kernel 2: fused scores + softmax -> fp16 attn. (R15, unchanged — passing)
// ---------------------------------------------------------------------------
#define SSTR 516

__global__ __launch_bounds__(256) void scores_softmax_kernel(
    const float* __restrict__ Va)
{
    extern __shared__ float smem[];
    float* hs = smem;                 // 8  * SSTR
    float* ss = smem + 8 * SSTR;      // 16 * SSTR
    float* va = smem + 24 * SSTR;     // 512

    const int b   = blockIdx.y;
    const int t0  = blockIdx.x * 8;
    const int tid = threadIdx.x;

    const int ti   = tid >> 5;
    const int si   = tid & 31;
    const int sh   = si >> 4;
    const int sl   = si & 15;
    const int aoff = sh * 256;

    va[tid]       = Va[tid];
    va[tid + 256] = Va[tid + 256];

#pragma unroll
    for (int r = 0; r < 4; r++) {
        int idx  = r * 256 + tid;
        int row  = idx >> 7;
        int col4 = idx & 127;
        float4 v = *(const float4*)(g_hpart + ((t0 + row) * BATCH + b) * ATT + col4 * 4);
        *(float4*)(hs + row * SSTR + col4 * 4) = v;
    }

    float sc[4];

#pragma unroll
    for (int c = 0; c < 4; c++) {
        __syncthreads();
#pragma unroll
        for (int r = 0; r < 8; r++) {
            int idx  = r * 256 + tid;
            int row  = idx >> 7;
            int col4 = idx & 127;
            float4 v = *(const float4*)(g_spart + ((c * 16 + row) * BATCH + b) * ATT + col4 * 4);
            *(float4*)(ss + row * SSTR + col4 * 4) = v;
        }
        __syncthreads();

        const float* hp = hs + ti * SSTR + aoff;
        const float* sp = ss + sl * SSTR + aoff;
        const float* vp = va + aoff;
        float acc = 0.f;
#pragma unroll 4
        for (int a = 0; a < 256; a += 4) {
            float4 h4 = *(const float4*)(hp + a);
            float4 s4 = *(const float4*)(sp + a);
            float4 v4 = *(const float4*)(vp + a);
            acc = fmaf(tanh_fast(h4.x + s4.x), v4.x, acc);
            acc = fmaf(tanh_fast(h4.y + s4.y), v4.y, acc);
            acc = fmaf(tanh_fast(h4.z + s4.z), v4.z, acc);
            acc = fmaf(tanh_fast(h4.w + s4.w), v4.w, acc);
        }
        sc[c] = acc;
    }

#pragma unroll
    for (int c = 0; c < 4; c++)
        sc[c] += __shfl_xor_sync(0xffffffffu, sc[c], 16);

    float mx = fmaxf(fmaxf(sc[0], sc[1]), fmaxf(sc[2], sc[3]));
#pragma unroll
    for (int o = 1; o <= 8; o <<= 1)
        mx = fmaxf(mx, __shfl_xor_sync(0xffffffffu, mx, o));

    float e[4], sum = 0.f;
#pragma unroll
    for (int c = 0; c < 4; c++) { e[c] = __expf(sc[c] - mx); sum += e[c]; }
#pragma unroll
    for (int o = 1; o <= 8; o <<= 1)
        sum += __shfl_xor_sync(0xffffffffu, sum, o);

    const float inv = 1.0f / sum;
    if (sh == 0) {
        __half* dst = g_attn + ((t0 + ti) * BATCH + b) * SRC;
#pragma unroll
        for (int c = 0; c < 4; c++)
            dst[c * 16 + sl] = __float2half_rn(e[c] * inv);
    }
}

// ---------------------------------------------------------------------------
// Kernel 3: fp16 tensor-core context. (R15, unchanged — passing)
// ---------------------------------------------------------------------------
#define CTH 72

__global__ __launch_bounds__(128) void context_kernel(
    float* __restrict__ out)
{
    extern __shared__ __align__(16) __half csm[];
    const uint32_t atb = smem_u32(csm);
    const uint32_t stb = atb + (uint32_t)(32 * CTH) * 2u;

    const int hc  = blockIdx.x;
    const int th  = blockIdx.y;
    const int b   = blockIdx.z;
    const int h0  = hc * 64;
    const int tt0 = th * 32;
    const int tid = threadIdx.x;
    const int lane = tid & 31;
    const int wid  = tid >> 5;

#pragma unroll
    for (int r = 0; r < 2; r++) {
        const int idx = r * 128 + tid;
        const int row = idx >> 3, c = idx & 7;
        CP_ASYNC16(atb + (uint32_t)(row * CTH + c * 8) * 2u,
                   g_attn + ((tt0 + row) * BATCH + b) * SRC + c * 8);
    }
#pragma unroll
    for (int r = 0; r < 4; r++) {
        const int idx = r * 128 + tid;
        const int row = idx >> 3, c = idx & 7;
        CP_ASYNC16(stb + (uint32_t)(row * CTH + c * 8) * 2u,
                   g_SrcT + (b * HID + h0 + row) * SRC + c * 8);
    }
    CP_COMMIT(); CP_WAIT0();
    __syncthreads();

    const uint32_t aoff = atb + (uint32_t)(((lane & 15) * CTH + ((lane >> 4) << 3)) * 2);
    const uint32_t boff = stb + (uint32_t)(((wid * 16 + (((lane >> 4) & 1) << 3) + (lane & 7)) * CTH
                                            + (((lane >> 3) & 1) << 3)) * 2);

    float acc[2][2][4];
#pragma unroll
    for (int mi = 0; mi < 2; mi++)
#pragma unroll
        for (int ni = 0; ni < 2; ni++)
#pragma unroll
            for (int j = 0; j < 4; j++) acc[mi][ni][j] = 0.f;

#pragma unroll
    for (int ks = 0; ks < 4; ks++) {
        const uint32_t koff = (uint32_t)(ks * 32);
        uint32_t a[2][4], b4[4];
        LDSM_X4(a[0], aoff + koff);
        LDSM_X4(a[1], aoff + (uint32_t)(16 * CTH * 2) + koff);
        LDSM_X4(b4, boff + koff);
#pragma unroll
        for (int mi = 0; mi < 2; mi++)
#pragma unroll
            for (int ni = 0; ni < 2; ni++)
                mma_f16(acc[mi][ni], a[mi], &b4[ni * 2]);
    }

    const int g  = lane >> 2;
    const int tg = lane & 3;
#pragma unroll
    for (int mi = 0; mi < 2; mi++) {
#pragma unroll
        for (int ni = 0; ni < 2; ni++) {
            const int t   = tt0 + mi * 16 + g;
            const int col = h0 + wid * 16 + ni * 8 + 2 * tg;
            *(float2*)(out + (t * BATCH + b) * HID + col)       = make_float2(acc[mi][ni][0], acc[mi][ni][1]);
            *(float2*)(out + ((t + 8) * BATCH + b) * HID + col) = make_float2(acc[mi][ni][2], acc[mi][ni][3]);
        }
    }
}

// ---------------------------------------------------------------------------
extern "C" void kernel_launch(void* const* d_in, const int* in_sizes, int n_in,
                              void* d_out, int out_size)
{
    const float* h_t  = (const float*)d_in[0];   // (64, 32, 512)
    const float* srce = (const float*)d_in[1];   // (64, 32, 512)
    const float* Wa   = (const float*)d_in[2];   // (1024, 512)
    const float* Va   = (const float*)d_in[3];   // (512,)
    float* out = (float*)d_out;                  // (64, 32, 512)

    (void)in_sizes; (void)n_in; (void)out_size;

    // 0) fp16 pre-pass v2: 512 blocks, vectorized transposed stores
    prep_fp16<<<512, 256>>>(h_t, srce, Wa);

    // 1) fp16 GEMMs (ldmatrix): grid (8 n, 32 m) = 256 CTAs, 2/SM
    const int gemm_smem = 3 * STGH * (int)sizeof(__half);   // 82944 B
    cudaFuncSetAttribute(gemm_mma_h,
                         cudaFuncAttributeMaxDynamicSharedMemorySize, gemm_smem);
    gemm_mma_h<<<dim3(8, 32), 256, gemm_smem>>>();

    // 2) fused scores + softmax: grid (8 t-tiles, 32 b) = 256 blocks
    const int sc_smem = (24 * SSTR + 512) * (int)sizeof(float);
    cudaFuncSetAttribute(scores_softmax_kernel,
                         cudaFuncAttributeMaxDynamicSharedMemorySize, sc_smem);
    scores_softmax_kernel<<<dim3(8, 32), 256, sc_smem>>>(Va);

    // 3) fp16 mma context: grid (8 hc, 2 th, 32 b) = 512 blocks, 128 thr
    const int ctx_smem = (32 + 64) * CTH * (int)sizeof(__half);   // 13824 B
    cudaFuncSetAttribute(context_kernel,
                         cudaFuncAttributeMaxDynamicSharedMemorySize, ctx_smem);
    context_kernel<<<dim3(8, 2, 32), 128, ctx_smem>>>(out);
}